// round 1
// baseline (speedup 1.0000x reference)
#include <cuda_runtime.h>

#define NROWS 8192
#define DM 14
#define MF 36
#define HH 256
#define FFD 2048
#define EPS 1e-5f
#define TK 512

// persistent scratch (device globals — no allocation allowed)
__device__ float g_h[NROWS * DM];
__device__ float g_q[NROWS * DM];
__device__ float g_k[NROWS * DM];
__device__ float g_v[NROWS * DM];
__device__ float g_sizef[NROWS];

// ---------------- warp helpers ----------------
__device__ __forceinline__ float wsum(float v) {
#pragma unroll
    for (int o = 16; o; o >>= 1) v += __shfl_xor_sync(0xffffffffu, v, o);
    return v;
}
__device__ __forceinline__ float wmax(float v) {
#pragma unroll
    for (int o = 16; o; o >>= 1) v = fmaxf(v, __shfl_xor_sync(0xffffffffu, v, o));
    return v;
}
__device__ __forceinline__ float4 wsum4(float4 v) {
    v.x = wsum(v.x); v.y = wsum(v.y); v.z = wsum(v.z); v.w = wsum(v.w);
    return v;
}
__device__ __forceinline__ void scale4(float4& v, float c) {
    v.x *= c; v.y *= c; v.z *= c; v.w *= c;
}
__device__ __forceinline__ void fma4(float4& a, float p, float4 v) {
    a.x = fmaf(p, v.x, a.x); a.y = fmaf(p, v.y, a.y);
    a.z = fmaf(p, v.z, a.z); a.w = fmaf(p, v.w, a.w);
}
// 14-element dot (elements 14,15 are zero padding, skipped)
__device__ __forceinline__ float dot14(const float4 a0, const float4 a1, const float4 a2, const float4 a3,
                                       const float4 b0, const float4 b1, const float4 b2, const float4 b3) {
    float s0 = a0.x * b0.x;
    s0 = fmaf(a0.y, b0.y, s0); s0 = fmaf(a0.z, b0.z, s0); s0 = fmaf(a0.w, b0.w, s0);
    s0 = fmaf(a1.x, b1.x, s0); s0 = fmaf(a1.y, b1.y, s0); s0 = fmaf(a1.z, b1.z, s0);
    float s1 = a1.w * b1.w;
    s1 = fmaf(a2.x, b2.x, s1); s1 = fmaf(a2.y, b2.y, s1); s1 = fmaf(a2.z, b2.z, s1);
    s1 = fmaf(a2.w, b2.w, s1); s1 = fmaf(a3.x, b3.x, s1); s1 = fmaf(a3.y, b3.y, s1);
    return s0 + s1;
}

// ---------------- QKV projection ----------------
// h[64 rows] x Wqkv^T + b -> g_q (pre-scaled by D^-0.5), g_k, g_v
__global__ void __launch_bounds__(256, 1)
qkv_kernel(const float* __restrict__ x0, int use_x,
           const float* __restrict__ W, const float* __restrict__ b) {
    __shared__ float Ws[42 * 14];
    __shared__ float bs[42];
    __shared__ float hs[64 * 14];
    const float* hin = use_x ? x0 : g_h;
    const int t = threadIdx.x;
    const int rb = blockIdx.x * 64;
    for (int i = t; i < 588; i += 256) Ws[i] = W[i];
    if (t < 42) bs[t] = b[t];
    for (int i = t; i < 64 * 14; i += 256) hs[i] = hin[rb * DM + i];
    __syncthreads();
    const float scale = rsqrtf(14.0f);
    for (int idx = t; idx < 64 * 42; idx += 256) {
        int r = idx / 42, c = idx % 42;
        float s = bs[c];
#pragma unroll
        for (int d = 0; d < 14; d++) s = fmaf(hs[r * 14 + d], Ws[c * 14 + d], s);
        int row = rb + r;
        int dd = c % 14;
        if (c < 14)      g_q[row * DM + dd] = s * scale;
        else if (c < 28) g_k[row * DM + dd] = s;
        else             g_v[row * DM + dd] = s;
    }
}

// ---------------- Flash attention + out-proj + residual + LN1 ----------------
// 128 CTAs x 512 threads; each warp owns 4 queries; K/V streamed in smem tiles.
__global__ void __launch_bounds__(512, 1)
attn_kernel(const float* __restrict__ x0, int use_x,
            const float* __restrict__ Wo, const float* __restrict__ bo,
            const float* __restrict__ lng, const float* __restrict__ lnb) {
    extern __shared__ float sm[];
    float* Ks  = sm;                   // TK*16
    float* Vs  = Ks + TK * 16;         // TK*16
    float* qs  = Vs + TK * 16;         // 64*16
    float* as_ = qs + 64 * 16;         // 64*16
    float* wos = as_ + 64 * 16;        // 196
    float* bos = wos + 196;            // 16

    const float* hin = use_x ? x0 : g_h;
    const int t = threadIdx.x, lane = t & 31, warp = t >> 5;
    const int qbase = blockIdx.x * 64;

    for (int i = t; i < 64 * 16; i += 512) {
        int r = i >> 4, d = i & 15;
        qs[i] = (d < DM) ? g_q[(qbase + r) * DM + d] : 0.f;
    }
    if (t < 196) wos[t] = Wo[t];
    if (t < 14)  bos[t] = bo[t];

    const int q0 = warp * 4;
    float4 acc[4][4];
#pragma unroll
    for (int qi = 0; qi < 4; qi++)
#pragma unroll
        for (int i = 0; i < 4; i++) acc[qi][i] = make_float4(0.f, 0.f, 0.f, 0.f);
    float m[4] = {-1e30f, -1e30f, -1e30f, -1e30f};
    float l[4] = {0.f, 0.f, 0.f, 0.f};

    __syncthreads();

    for (int cb = 0; cb < NROWS; cb += TK) {
        for (int i = t; i < TK * 16; i += 512) {
            int j = i >> 4, d = i & 15;
            int g = (cb + j) * DM + d;
            Ks[i] = (d < DM) ? g_k[g] : 0.f;
            Vs[i] = (d < DM) ? g_v[g] : 0.f;
        }
        __syncthreads();

        for (int kk = lane; kk < TK; kk += 32) {
            const float4* kp = reinterpret_cast<const float4*>(Ks + (kk << 4));
            float4 k0 = kp[0], k1 = kp[1], k2 = kp[2], k3 = kp[3];
            float s[4];
#pragma unroll
            for (int qi = 0; qi < 4; qi++) {
                const float4* qp = reinterpret_cast<const float4*>(qs + ((q0 + qi) << 4));
                s[qi] = dot14(qp[0], qp[1], qp[2], qp[3], k0, k1, k2, k3);
            }
            const float4* vp = reinterpret_cast<const float4*>(Vs + (kk << 4));
            float4 v0 = vp[0], v1 = vp[1], v2 = vp[2], v3 = vp[3];
#pragma unroll
            for (int qi = 0; qi < 4; qi++) {
                float sv = s[qi], p;
                if (sv > m[qi]) {
                    float c = __expf(m[qi] - sv);
                    l[qi] *= c;
                    scale4(acc[qi][0], c); scale4(acc[qi][1], c);
                    scale4(acc[qi][2], c);
                    acc[qi][3].x *= c; acc[qi][3].y *= c;
                    m[qi] = sv; p = 1.f;
                } else {
                    p = __expf(sv - m[qi]);
                }
                l[qi] += p;
                fma4(acc[qi][0], p, v0); fma4(acc[qi][1], p, v1); fma4(acc[qi][2], p, v2);
                acc[qi][3].x = fmaf(p, v3.x, acc[qi][3].x);
                acc[qi][3].y = fmaf(p, v3.y, acc[qi][3].y);
            }
        }
        __syncthreads();
    }

    // cross-lane combine per query (online-softmax merge)
#pragma unroll
    for (int qi = 0; qi < 4; qi++) {
        float gm = wmax(m[qi]);
        float c = __expf(m[qi] - gm);
        float ll = wsum(l[qi] * c);
        scale4(acc[qi][0], c); scale4(acc[qi][1], c); scale4(acc[qi][2], c); scale4(acc[qi][3], c);
        float4 A0 = wsum4(acc[qi][0]);
        float4 A1 = wsum4(acc[qi][1]);
        float4 A2 = wsum4(acc[qi][2]);
        float4 A3 = wsum4(acc[qi][3]);
        if (lane == 0) {
            float inv = 1.f / ll;
            float* ap = as_ + ((q0 + qi) << 4);
            ap[0] = A0.x * inv; ap[1] = A0.y * inv; ap[2]  = A0.z * inv; ap[3]  = A0.w * inv;
            ap[4] = A1.x * inv; ap[5] = A1.y * inv; ap[6]  = A1.z * inv; ap[7]  = A1.w * inv;
            ap[8] = A2.x * inv; ap[9] = A2.y * inv; ap[10] = A2.z * inv; ap[11] = A2.w * inv;
            ap[12] = A3.x * inv; ap[13] = A3.y * inv;
        }
    }
    __syncthreads();

    // out-projection + residual + LN1 (one thread per row)
    if (t < 64) {
        int row = qbase + t;
        float a[14];
#pragma unroll
        for (int d = 0; d < 14; d++) a[d] = as_[(t << 4) + d];
        float pre[14];
        float mu = 0.f;
#pragma unroll
        for (int d2 = 0; d2 < 14; d2++) {
            float o = bos[d2];
#pragma unroll
            for (int d = 0; d < 14; d++) o = fmaf(a[d], wos[d2 * 14 + d], o);
            o += hin[row * DM + d2];
            pre[d2] = o;
            mu += o;
        }
        mu *= (1.f / 14.f);
        float var = 0.f;
#pragma unroll
        for (int d = 0; d < 14; d++) { float z = pre[d] - mu; var = fmaf(z, z, var); }
        var *= (1.f / 14.f);
        float rs = rsqrtf(var + EPS);
#pragma unroll
        for (int d = 0; d < 14; d++)
            g_h[row * DM + d] = (pre[d] - mu) * rs * __ldg(lng + d) + __ldg(lnb + d);
    }
}

// ---------------- Fused FFN (14->2048->14) + residual + LN2 ----------------
// Both weight matrices (224KB) live in smem; 64 rows per CTA in batches of 4.
__global__ void __launch_bounds__(256, 1)
ffn_kernel(const float* __restrict__ W1, const float* __restrict__ b1,
           const float* __restrict__ W2, const float* __restrict__ b2,
           const float* __restrict__ lng, const float* __restrict__ lnb) {
    extern __shared__ float sm[];
    float* W1s   = sm;              // 28672  [j*14+d]
    float* W2s   = W1s + 28672;     // 28672  [d*2048+j]
    float* hs    = W2s + 28672;     // 64
    float* red   = hs + 64;         // 448
    float* pre   = red + 448;       // 64
    float* stats = pre + 64;        // 8

    const int t = threadIdx.x, lane = t & 31, warp = t >> 5;
    for (int i = t; i < 28672; i += 256) { W1s[i] = W1[i]; W2s[i] = W2[i]; }
    const int rbase = blockIdx.x * 64;
    float b1t[8];
#pragma unroll
    for (int jj = 0; jj < 8; jj++) b1t[jj] = __ldg(b1 + jj * 256 + t);
    __syncthreads();

    for (int batch = 0; batch < 64; batch += 4) {
        int r0 = rbase + batch;
        if (t < 56) hs[t] = g_h[r0 * DM + t];
        __syncthreads();

        float hr[4][14];
#pragma unroll
        for (int r = 0; r < 4; r++)
#pragma unroll
            for (int d = 0; d < 14; d++) hr[r][d] = hs[r * 14 + d];

        float po[14][4];
#pragma unroll
        for (int d = 0; d < 14; d++)
#pragma unroll
            for (int r = 0; r < 4; r++) po[d][r] = 0.f;

#pragma unroll
        for (int jj = 0; jj < 8; jj++) {
            int j = jj * 256 + t;
            float w1[14];
#pragma unroll
            for (int d = 0; d < 14; d++) w1[d] = W1s[j * 14 + d];
            float hj[4];
#pragma unroll
            for (int r = 0; r < 4; r++) {
                float s = b1t[jj];
#pragma unroll
                for (int d = 0; d < 14; d++) s = fmaf(hr[r][d], w1[d], s);
                hj[r] = fmaxf(s, 0.f);
            }
#pragma unroll
            for (int d = 0; d < 14; d++) {
                float w2 = W2s[d * 2048 + j];
#pragma unroll
                for (int r = 0; r < 4; r++) po[d][r] = fmaf(hj[r], w2, po[d][r]);
            }
        }
        // warp-level then cross-warp reduction
#pragma unroll
        for (int d = 0; d < 14; d++)
#pragma unroll
            for (int r = 0; r < 4; r++) po[d][r] = wsum(po[d][r]);
        if (lane == 0) {
#pragma unroll
            for (int d = 0; d < 14; d++)
#pragma unroll
                for (int r = 0; r < 4; r++) red[warp * 56 + d * 4 + r] = po[d][r];
        }
        __syncthreads();
        if (t < 56) {
            int d = t >> 2, r = t & 3;
            float s = __ldg(b2 + d) + hs[r * 14 + d];   // bias + residual
            for (int w = 0; w < 8; w++) s += red[w * 56 + t];
            pre[r * 14 + d] = s;
        }
        __syncthreads();
        if (t < 4) {
            float mu = 0.f;
            for (int d = 0; d < 14; d++) mu += pre[t * 14 + d];
            mu *= (1.f / 14.f);
            float var = 0.f;
            for (int d = 0; d < 14; d++) { float z = pre[t * 14 + d] - mu; var = fmaf(z, z, var); }
            var *= (1.f / 14.f);
            stats[t * 2] = mu;
            stats[t * 2 + 1] = rsqrtf(var + EPS);
        }
        __syncthreads();
        if (t < 56) {
            int r = t / 14, d = t % 14;
            g_h[(r0 + r) * DM + d] =
                (pre[r * 14 + d] - stats[r * 2]) * stats[r * 2 + 1] * __ldg(lng + d) + __ldg(lnb + d);
        }
        __syncthreads();
    }
}

// ---------------- head 1: size_out = fc2(fc1(h)) ----------------
__global__ void __launch_bounds__(256, 1)
head1_kernel(const float* __restrict__ w1, const float* __restrict__ b1f,
             const float* __restrict__ w2, const float* __restrict__ b2f,
             float* __restrict__ out) {
    int n = blockIdx.x * 256 + threadIdx.x;
    float h[14];
#pragma unroll
    for (int d = 0; d < 14; d++) h[d] = g_h[n * DM + d];
    float size = __ldg(b2f);
#pragma unroll
    for (int d2 = 0; d2 < 14; d2++) {
        float s = __ldg(b1f + d2);
#pragma unroll
        for (int d = 0; d < 14; d++) s = fmaf(h[d], __ldg(w1 + d2 * 14 + d), s);
        size = fmaf(s, __ldg(w2 + d2), size);
    }
    out[n] = size;
    g_sizef[n] = (float)(int)size;   // trunc toward zero, like .astype(int32)
}

// ---------------- head 2: reg MLP 51->256->256->1 + mask ----------------
__global__ void __launch_bounds__(256, 1)
head2_kernel(const float* __restrict__ x, const float* __restrict__ y,
             const float* __restrict__ w3, const float* __restrict__ b3,
             const float* __restrict__ w4, const float* __restrict__ b4,
             const float* __restrict__ w5, const float* __restrict__ b5,
             float* __restrict__ out) {
    extern __shared__ float sm[];
    float* w3s = sm;            // 13056 [t*51+i]
    float* r1s = w3s + 13056;   // 4096  [r*256+t]
    float* ins = r1s + 4096;    // 816   [r*51+i]
    float* red = ins + 816;     // 128

    const int t = threadIdx.x, lane = t & 31, warp = t >> 5;
    const int rbase = blockIdx.x * 16;
    for (int i = t; i < 13056; i += 256) w3s[i] = w3[i];
    for (int i = t; i < 16 * 51; i += 256) {
        int r = i / 51, c = i % 51, row = rbase + r;
        float v;
        if (c == 0)      v = g_sizef[row];
        else if (c < 15) v = x[row * DM + c - 1];
        else             v = y[row * MF + c - 15];
        ins[i] = v;
    }
    __syncthreads();

    // stage A: r1[t] = relu(fc3 . in + b3), 16 rows
    float r1a[16];
    float b3t = __ldg(b3 + t);
#pragma unroll
    for (int r = 0; r < 16; r++) r1a[r] = b3t;
    for (int i = 0; i < 51; i++) {
        float w = w3s[t * 51 + i];
#pragma unroll
        for (int r = 0; r < 16; r++) r1a[r] = fmaf(ins[r * 51 + i], w, r1a[r]);
    }
#pragma unroll
    for (int r = 0; r < 16; r++) r1s[r * 256 + t] = fmaxf(r1a[r], 0.f);
    __syncthreads();

    // stage B: r2[t] = relu(fc4 . r1 + b4), fc4 row streamed from L2
    float r2a[16];
    float b4t = __ldg(b4 + t);
#pragma unroll
    for (int r = 0; r < 16; r++) r2a[r] = b4t;
    const float* w4r = w4 + t * 256;
#pragma unroll 4
    for (int j = 0; j < 256; j++) {
        float w = __ldg(w4r + j);
#pragma unroll
        for (int r = 0; r < 16; r++) r2a[r] = fmaf(r1s[r * 256 + j], w, r2a[r]);
    }

    // stage C: reg = fc5 . relu(r2) + b5, reduce across 256 threads
    float w5t = __ldg(w5 + t);
#pragma unroll
    for (int r = 0; r < 16; r++) {
        float v = fmaxf(r2a[r], 0.f) * w5t;
        v = wsum(v);
        if (lane == 0) red[warp * 16 + r] = v;
    }
    __syncthreads();
    if (t < 16) {
        float s = __ldg(b5);
        for (int w = 0; w < 8; w++) s += red[w * 16 + t];
        int row = rbase + t;
        out[NROWS + row] = (g_sizef[row] != 0.f) ? s : 0.f;
    }
}

// ---------------- launcher ----------------
extern "C" void kernel_launch(void* const* d_in, const int* in_sizes, int n_in,
                              void* d_out, int out_size) {
    const float* x    = (const float*)d_in[0];
    const float* y    = (const float*)d_in[1];
    const float* wqkv = (const float*)d_in[2];
    const float* bqkv = (const float*)d_in[3];
    const float* wo   = (const float*)d_in[4];
    const float* bo   = (const float*)d_in[5];
    const float* ln1g = (const float*)d_in[6];
    const float* ln1b = (const float*)d_in[7];
    const float* ffw1 = (const float*)d_in[8];
    const float* ffb1 = (const float*)d_in[9];
    const float* ffw2 = (const float*)d_in[10];
    const float* ffb2 = (const float*)d_in[11];
    const float* ln2g = (const float*)d_in[12];
    const float* ln2b = (const float*)d_in[13];
    const float* fc1w = (const float*)d_in[14];
    const float* fc1b = (const float*)d_in[15];
    const float* fc2w = (const float*)d_in[16];
    const float* fc2b = (const float*)d_in[17];
    const float* fc3w = (const float*)d_in[18];
    const float* fc3b = (const float*)d_in[19];
    const float* fc4w = (const float*)d_in[20];
    const float* fc4b = (const float*)d_in[21];
    const float* fc5w = (const float*)d_in[22];
    const float* fc5b = (const float*)d_in[23];
    float* out = (float*)d_out;

    const int attn_smem = (TK * 16 * 2 + 64 * 16 * 2 + 196 + 16) * (int)sizeof(float);
    const int ffn_smem  = (28672 * 2 + 64 + 448 + 64 + 8) * (int)sizeof(float);
    const int h2_smem   = (13056 + 4096 + 816 + 128) * (int)sizeof(float);
    cudaFuncSetAttribute(attn_kernel, cudaFuncAttributeMaxDynamicSharedMemorySize, attn_smem);
    cudaFuncSetAttribute(ffn_kernel,  cudaFuncAttributeMaxDynamicSharedMemorySize, ffn_smem);
    cudaFuncSetAttribute(head2_kernel, cudaFuncAttributeMaxDynamicSharedMemorySize, h2_smem);

    for (int l = 0; l < 2; l++) {
        qkv_kernel<<<128, 256>>>(x, (l == 0) ? 1 : 0, wqkv + l * 588, bqkv + l * 42);
        attn_kernel<<<128, 512, attn_smem>>>(x, (l == 0) ? 1 : 0,
                                             wo + l * 196, bo + l * 14,
                                             ln1g + l * 14, ln1b + l * 14);
        ffn_kernel<<<128, 256, ffn_smem>>>(ffw1 + l * 28672, ffb1 + l * 2048,
                                           ffw2 + l * 28672, ffb2 + l * 14,
                                           ln2g + l * 14, ln2b + l * 14);
    }
    head1_kernel<<<32, 256>>>(fc1w, fc1b, fc2w, fc2b, out);
    head2_kernel<<<512, 256, h2_smem>>>(x, y, fc3w, fc3b, fc4w, fc4b, fc5w, fc5b, out);
}

// round 2
// speedup vs baseline: 2.1500x; 2.1500x over previous
#include <cuda_runtime.h>
#include <stdint.h>

#define NROWS 8192
#define DM 14
#define MF 36
#define HH 256
#define FFD 2048
#define EPS 1e-5f
#define TK 512
#define KSTRIDE 514           // padded float2 stride per d2 row (conflict-free)
#define TILE_F2 (7 * KSTRIDE) // 3598 float2 per buffer

typedef unsigned long long u64;

// persistent scratch (device globals — no allocation allowed)
__device__ __align__(16) float g_h[NROWS * DM];
__device__ __align__(16) float g_q[NROWS * DM];   // pre-scaled by D^-0.5 * log2(e)
__device__ __align__(16) float g_k[NROWS * DM];
__device__ __align__(16) float g_v[NROWS * DM];
__device__ float g_sizef[NROWS];
__device__ float g_qn[NROWS];        // |q_scaled| per row
__device__ float g_kmaxpart[32];     // per-block max |k|^2

// ---------------- f32x2 helpers ----------------
__device__ __forceinline__ u64 f2u(float2 v) { union { float2 f; u64 u; } c; c.f = v; return c.u; }
__device__ __forceinline__ float2 u2f(u64 u) { union { float2 f; u64 u; } c; c.u = u; return c.f; }
__device__ __forceinline__ u64 pack2(float lo, float hi) { float2 v; v.x = lo; v.y = hi; return f2u(v); }
__device__ __forceinline__ u64 fma2(u64 a, u64 b, u64 c) {
    u64 d; asm("fma.rn.f32x2 %0,%1,%2,%3;" : "=l"(d) : "l"(a), "l"(b), "l"(c)); return d;
}
__device__ __forceinline__ u64 mul2(u64 a, u64 b) {
    u64 d; asm("mul.rn.f32x2 %0,%1,%2;" : "=l"(d) : "l"(a), "l"(b)); return d;
}
__device__ __forceinline__ float ex2f(float x) {
    float y; asm("ex2.approx.f32 %0,%1;" : "=f"(y) : "f"(x)); return y;
}
__device__ __forceinline__ void cp8(uint32_t dst, const void* src) {
    asm volatile("cp.async.ca.shared.global [%0], [%1], 8;" :: "r"(dst), "l"(src));
}
#define CP_COMMIT() asm volatile("cp.async.commit_group;")
#define CP_WAIT(N)  asm volatile("cp.async.wait_group %0;" :: "n"(N))

// ---------------- warp helpers ----------------
__device__ __forceinline__ float wsum(float v) {
#pragma unroll
    for (int o = 16; o; o >>= 1) v += __shfl_xor_sync(0xffffffffu, v, o);
    return v;
}
__device__ __forceinline__ float wmax(float v) {
#pragma unroll
    for (int o = 16; o; o >>= 1) v = fmaxf(v, __shfl_xor_sync(0xffffffffu, v, o));
    return v;
}

// ---------------- QKV projection ----------------
__global__ void __launch_bounds__(256, 1)
qkv_kernel(const float* __restrict__ x0, int use_x,
           const float* __restrict__ W, const float* __restrict__ b) {
    __shared__ float Ws[42 * 14];
    __shared__ float bs[42];
    __shared__ float hs[64 * 14];
    const float* hin = use_x ? x0 : g_h;
    const int t = threadIdx.x;
    const int rb = blockIdx.x * 64;
    for (int i = t; i < 588; i += 256) Ws[i] = W[i];
    if (t < 42) bs[t] = b[t];
    for (int i = t; i < 64 * 14; i += 256) hs[i] = hin[rb * DM + i];
    __syncthreads();
    const float scale = rsqrtf(14.0f) * 1.44269504f;   // fold log2(e) into q
    for (int idx = t; idx < 64 * 42; idx += 256) {
        int r = idx / 42, c = idx % 42;
        float s = bs[c];
#pragma unroll
        for (int d = 0; d < 14; d++) s = fmaf(hs[r * 14 + d], Ws[c * 14 + d], s);
        int row = rb + r;
        int dd = c % 14;
        if (c < 14)      g_q[row * DM + dd] = s * scale;
        else if (c < 28) g_k[row * DM + dd] = s;
        else             g_v[row * DM + dd] = s;
    }
}

// ---------------- prep: per-row |q|, global max |k|^2 (32 partials) ----------------
__global__ void __launch_bounds__(256, 1)
prep_kernel() {
    __shared__ float sp[8];
    const int t = threadIdx.x, lane = t & 31, warp = t >> 5;
    int r = blockIdx.x * 256 + t;
    float qn = 0.f, kn = 0.f;
#pragma unroll
    for (int d = 0; d < 14; d++) {
        float qf = g_q[r * DM + d]; qn = fmaf(qf, qf, qn);
        float kf = g_k[r * DM + d]; kn = fmaf(kf, kf, kn);
    }
    g_qn[r] = sqrtf(qn);
    kn = wmax(kn);
    if (lane == 0) sp[warp] = kn;
    __syncthreads();
    if (t == 0) {
        float m = sp[0];
#pragma unroll
        for (int w = 1; w < 8; w++) m = fmaxf(m, sp[w]);
        g_kmaxpart[blockIdx.x] = m;
    }
}

// ---------------- attention tile copy (cp.async, d-major float2, padded) ----------------
__device__ __forceinline__ void tile_cp(uint32_t ksb, uint32_t vsb, int buf, int cb, int t) {
    const float2* gk = ((const float2*)g_k) + cb * 7;
    const float2* gv = ((const float2*)g_v) + cb * 7;
    uint32_t kd = ksb + (uint32_t)buf * TILE_F2 * 8;
    uint32_t vd = vsb + (uint32_t)buf * TILE_F2 * 8;
#pragma unroll
    for (int s = 0; s < 14; s++) {
        int i = t + s * 256;                 // i < 3584
        int kk = i / 7;
        int d2 = i - kk * 7;
        uint32_t off = (uint32_t)(d2 * KSTRIDE + kk) * 8u;
        cp8(kd + off, gk + i);
        cp8(vd + off, gv + i);
    }
}

// ---------------- Flash attention (no-max softmax) + out-proj + residual + LN1 ----
// 128 persistent CTAs x 256 threads; 2 query-blocks of 32 per CTA; 4 queries/warp.
__global__ void __launch_bounds__(256, 1)
attn_kernel(const float* __restrict__ x0, int use_x,
            const float* __restrict__ Wo, const float* __restrict__ bo,
            const float* __restrict__ lng, const float* __restrict__ lnb) {
    extern __shared__ float sm[];
    float2* Ks2 = (float2*)sm;                 // 2 bufs x 3598 f2
    float2* Vs2 = (float2*)(sm + 2 * TILE_F2 * 2);
    float*  as_ = sm + 4 * TILE_F2 * 2;        // 32*16
    float*  wos = as_ + 512;                   // 196
    float*  bos = wos + 196;                   // 14

    const int t = threadIdx.x, lane = t & 31, warp = t >> 5;
    const uint32_t ksb = (uint32_t)__cvta_generic_to_shared(Ks2);
    const uint32_t vsb = (uint32_t)__cvta_generic_to_shared(Vs2);
    const float* hin = use_x ? x0 : g_h;

    if (t < 196) wos[t] = Wo[t];
    if (t < 14)  bos[t] = bo[t];

    // global max |k|
    float mk2 = 0.f;
#pragma unroll
    for (int i = 0; i < 32; i++) mk2 = fmaxf(mk2, __ldg(g_kmaxpart + i));
    const float maxk = sqrtf(mk2);

    for (int pass = 0; pass < 2; pass++) {
        const int qbase = (blockIdx.x + pass * 128) * 32;
        const int q0 = warp * 4;

        u64 q[4][7], o[4][7], init2[4];
        float l[4];
#pragma unroll
        for (int qi = 0; qi < 4; qi++) {
            int row = qbase + q0 + qi;
            const float2* qp = ((const float2*)g_q) + row * 7;
#pragma unroll
            for (int d2 = 0; d2 < 7; d2++) {
                q[qi][d2] = f2u(__ldg(qp + d2));
                o[qi][d2] = 0ull;
            }
            init2[qi] = pack2(-__ldg(g_qn + row) * maxk, 0.f);
            l[qi] = 0.f;
        }

        tile_cp(ksb, vsb, 0, 0, t);
        CP_COMMIT();

        for (int tile = 0; tile < 16; tile++) {
            if (tile < 15) {
                tile_cp(ksb, vsb, (tile + 1) & 1, (tile + 1) * TK, t);
                CP_COMMIT();
                CP_WAIT(1);
            } else {
                CP_WAIT(0);
            }
            __syncthreads();

            const float2* Kb = Ks2 + (tile & 1) * TILE_F2;
            const float2* Vb = Vs2 + (tile & 1) * TILE_F2;
            for (int kk = lane; kk < TK; kk += 32) {
                u64 k0 = f2u(Kb[0 * KSTRIDE + kk]);
                u64 k1 = f2u(Kb[1 * KSTRIDE + kk]);
                u64 k2 = f2u(Kb[2 * KSTRIDE + kk]);
                u64 k3 = f2u(Kb[3 * KSTRIDE + kk]);
                u64 k4 = f2u(Kb[4 * KSTRIDE + kk]);
                u64 k5 = f2u(Kb[5 * KSTRIDE + kk]);
                u64 k6 = f2u(Kb[6 * KSTRIDE + kk]);
                u64 v0 = f2u(Vb[0 * KSTRIDE + kk]);
                u64 v1 = f2u(Vb[1 * KSTRIDE + kk]);
                u64 v2 = f2u(Vb[2 * KSTRIDE + kk]);
                u64 v3 = f2u(Vb[3 * KSTRIDE + kk]);
                u64 v4 = f2u(Vb[4 * KSTRIDE + kk]);
                u64 v5 = f2u(Vb[5 * KSTRIDE + kk]);
                u64 v6 = f2u(Vb[6 * KSTRIDE + kk]);
#pragma unroll
                for (int qi = 0; qi < 4; qi++) {
                    u64 s2 = fma2(q[qi][0], k0, init2[qi]);
                    s2 = fma2(q[qi][1], k1, s2);
                    s2 = fma2(q[qi][2], k2, s2);
                    s2 = fma2(q[qi][3], k3, s2);
                    s2 = fma2(q[qi][4], k4, s2);
                    s2 = fma2(q[qi][5], k5, s2);
                    s2 = fma2(q[qi][6], k6, s2);
                    float2 sf = u2f(s2);
                    float p = ex2f(sf.x + sf.y);     // 2^(score*log2e - M2) — bounded <= 1-ish
                    l[qi] += p;
                    u64 p2 = pack2(p, p);
                    o[qi][0] = fma2(p2, v0, o[qi][0]);
                    o[qi][1] = fma2(p2, v1, o[qi][1]);
                    o[qi][2] = fma2(p2, v2, o[qi][2]);
                    o[qi][3] = fma2(p2, v3, o[qi][3]);
                    o[qi][4] = fma2(p2, v4, o[qi][4]);
                    o[qi][5] = fma2(p2, v5, o[qi][5]);
                    o[qi][6] = fma2(p2, v6, o[qi][6]);
                }
            }
            __syncthreads();
        }

        // cross-lane combine (shared M per query — simple sums)
#pragma unroll
        for (int qi = 0; qi < 4; qi++) {
            float ll = wsum(l[qi]);
            float av[14];
#pragma unroll
            for (int d2 = 0; d2 < 7; d2++) {
                float2 f = u2f(o[qi][d2]);
                av[2 * d2] = wsum(f.x);
                av[2 * d2 + 1] = wsum(f.y);
            }
            if (lane == 0) {
                float inv = 1.f / ll;
                float* ap = as_ + ((q0 + qi) << 4);
#pragma unroll
                for (int d = 0; d < 14; d++) ap[d] = av[d] * inv;
            }
        }
        __syncthreads();

        // out-projection + residual + LN1
        if (t < 32) {
            int row = qbase + t;
            float a[14];
#pragma unroll
            for (int d = 0; d < 14; d++) a[d] = as_[(t << 4) + d];
            float pre[14];
            float mu = 0.f;
#pragma unroll
            for (int d2 = 0; d2 < 14; d2++) {
                float ov = bos[d2];
#pragma unroll
                for (int d = 0; d < 14; d++) ov = fmaf(a[d], wos[d2 * 14 + d], ov);
                ov += hin[row * DM + d2];
                pre[d2] = ov;
                mu += ov;
            }
            mu *= (1.f / 14.f);
            float var = 0.f;
#pragma unroll
            for (int d = 0; d < 14; d++) { float z = pre[d] - mu; var = fmaf(z, z, var); }
            var *= (1.f / 14.f);
            float rs = rsqrtf(var + EPS);
#pragma unroll
            for (int d = 0; d < 14; d++)
                g_h[row * DM + d] = (pre[d] - mu) * rs * __ldg(lng + d) + __ldg(lnb + d);
        }
        __syncthreads();
    }
}

// ---------------- Fused FFN (14->2048->14) + residual + LN2, f32x2 ----------------
#define W1STRIDE 2049   // float2 stride per d2 row
__global__ void __launch_bounds__(256, 1)
ffn_kernel(const float* __restrict__ W1, const float* __restrict__ b1,
           const float* __restrict__ W2, const float* __restrict__ b2,
           const float* __restrict__ lng, const float* __restrict__ lnb) {
    extern __shared__ float sm[];
    float2* W1s2 = (float2*)sm;                 // 7 x 2049 f2 = 14343 f2
    float*  W2s  = sm + 2 * 7 * W1STRIDE;       // 28672  [d*2048+j]
    float*  hs   = W2s + 28672;                 // 64
    float*  red  = hs + 64;                     // 448
    float*  pre  = red + 448;                   // 56 (use 64)
    float*  stats = pre + 64;                   // 8

    const int t = threadIdx.x, lane = t & 31, warp = t >> 5;
    // load W1 transposed to d2-major float2, W2 linear
    {
        const float2* W1g = (const float2*)W1;
        for (int i = t; i < 14336; i += 256) {
            int j = i / 7, d2 = i - j * 7;
            W1s2[d2 * W1STRIDE + j] = W1g[i];
        }
        for (int i = t; i < 28672; i += 256) W2s[i] = W2[i];
    }
    const int rbase = blockIdx.x * 64;
    float b1t[8];
#pragma unroll
    for (int jj = 0; jj < 8; jj++) b1t[jj] = __ldg(b1 + jj * 256 + t);
    __syncthreads();

    for (int batch = 0; batch < 64; batch += 4) {
        int r0 = rbase + batch;
        if (t < 56) hs[t] = g_h[r0 * DM + t];
        __syncthreads();

        u64 hr2[4][7];
#pragma unroll
        for (int r = 0; r < 4; r++)
#pragma unroll
            for (int d2 = 0; d2 < 7; d2++) hr2[r][d2] = f2u(((const float2*)hs)[r * 7 + d2]);

        u64 po2[14][2];
#pragma unroll
        for (int d = 0; d < 14; d++) { po2[d][0] = 0ull; po2[d][1] = 0ull; }

        for (int jj = 0; jj < 8; jj++) {
            int j = jj * 256 + t;
            u64 w1v[7];
#pragma unroll
            for (int d2 = 0; d2 < 7; d2++) w1v[d2] = f2u(W1s2[d2 * W1STRIDE + j]);
            float hj[4];
#pragma unroll
            for (int r = 0; r < 4; r++) {
                u64 a = mul2(hr2[r][0], w1v[0]);
#pragma unroll
                for (int d2 = 1; d2 < 7; d2++) a = fma2(hr2[r][d2], w1v[d2], a);
                float2 af = u2f(a);
                hj[r] = fmaxf(af.x + af.y + b1t[jj], 0.f);
            }
            u64 hj01 = pack2(hj[0], hj[1]);
            u64 hj23 = pack2(hj[2], hj[3]);
#pragma unroll
            for (int d = 0; d < 14; d++) {
                float w2 = W2s[d * 2048 + j];
                u64 w2p = pack2(w2, w2);
                po2[d][0] = fma2(hj01, w2p, po2[d][0]);
                po2[d][1] = fma2(hj23, w2p, po2[d][1]);
            }
        }
        // reductions
#pragma unroll
        for (int d = 0; d < 14; d++) {
            float2 a = u2f(po2[d][0]);
            float2 b = u2f(po2[d][1]);
            float v0 = wsum(a.x), v1 = wsum(a.y), v2 = wsum(b.x), v3 = wsum(b.y);
            if (lane == 0) {
                red[warp * 56 + d * 4 + 0] = v0;
                red[warp * 56 + d * 4 + 1] = v1;
                red[warp * 56 + d * 4 + 2] = v2;
                red[warp * 56 + d * 4 + 3] = v3;
            }
        }
        __syncthreads();
        if (t < 56) {
            int d = t >> 2, r = t & 3;
            float s = __ldg(b2 + d) + hs[r * 14 + d];
            for (int w = 0; w < 8; w++) s += red[w * 56 + t];
            pre[r * 14 + d] = s;
        }
        __syncthreads();
        if (t < 4) {
            float mu = 0.f;
            for (int d = 0; d < 14; d++) mu += pre[t * 14 + d];
            mu *= (1.f / 14.f);
            float var = 0.f;
            for (int d = 0; d < 14; d++) { float z = pre[t * 14 + d] - mu; var = fmaf(z, z, var); }
            var *= (1.f / 14.f);
            stats[t * 2] = mu;
            stats[t * 2 + 1] = rsqrtf(var + EPS);
        }
        __syncthreads();
        if (t < 56) {
            int r = t / 14, d = t % 14;
            g_h[(r0 + r) * DM + d] =
                (pre[r * 14 + d] - stats[r * 2]) * stats[r * 2 + 1] * __ldg(lng + d) + __ldg(lnb + d);
        }
        __syncthreads();
    }
}

// ---------------- head 1 ----------------
__global__ void __launch_bounds__(256, 1)
head1_kernel(const float* __restrict__ w1, const float* __restrict__ b1f,
             const float* __restrict__ w2, const float* __restrict__ b2f,
             float* __restrict__ out) {
    int n = blockIdx.x * 256 + threadIdx.x;
    float h[14];
#pragma unroll
    for (int d = 0; d < 14; d++) h[d] = g_h[n * DM + d];
    float size = __ldg(b2f);
#pragma unroll
    for (int d2 = 0; d2 < 14; d2++) {
        float s = __ldg(b1f + d2);
#pragma unroll
        for (int d = 0; d < 14; d++) s = fmaf(h[d], __ldg(w1 + d2 * 14 + d), s);
        size = fmaf(s, __ldg(w2 + d2), size);
    }
    out[n] = size;
    g_sizef[n] = (float)(int)size;
}

// ---------------- head 2: 51->256->256->1, w4 smem-staged, f32x2 ----------------
__global__ void __launch_bounds__(256, 1)
head2_kernel(const float* __restrict__ x, const float* __restrict__ y,
             const float* __restrict__ w3, const float* __restrict__ b3,
             const float* __restrict__ w4, const float* __restrict__ b4,
             const float* __restrict__ w5, const float* __restrict__ b5,
             float* __restrict__ out) {
    extern __shared__ float sm[];
    float* w3s   = sm;             // 13056 [t*51+i]
    float* ins   = w3s + 13056;    // 816
    float* red   = ins + 816;      // 128
    float* r1f   = red + 128;      // r1 pairs: 256 x 9 f2 = 4608 floats
    float* w4s   = r1f + 4608;     // 256 x 65 = 16640

    const int t = threadIdx.x, lane = t & 31, warp = t >> 5;
    const int rbase = blockIdx.x * 16;
    for (int i = t; i < 13056; i += 256) w3s[i] = w3[i];
    for (int i = t; i < 16 * 51; i += 256) {
        int r = i / 51, c = i % 51, row = rbase + r;
        float v;
        if (c == 0)      v = g_sizef[row];
        else if (c < 15) v = x[row * DM + c - 1];
        else             v = y[row * MF + c - 15];
        ins[i] = v;
    }
    __syncthreads();

    // stage A: r1[neuron t][16 rows]
    float r1a[16];
    float b3t = __ldg(b3 + t);
#pragma unroll
    for (int r = 0; r < 16; r++) r1a[r] = b3t;
    for (int i = 0; i < 51; i++) {
        float w = w3s[t * 51 + i];
#pragma unroll
        for (int r = 0; r < 16; r++) r1a[r] = fmaf(ins[r * 51 + i], w, r1a[r]);
    }
#pragma unroll
    for (int rp = 0; rp < 8; rp++) {
        float2 v;
        v.x = fmaxf(r1a[2 * rp], 0.f);
        v.y = fmaxf(r1a[2 * rp + 1], 0.f);
        ((float2*)r1f)[t * 9 + rp] = v;
    }
    __syncthreads();

    // stage B: r2[o=t][rows], w4 staged through smem chunks of 64
    u64 r2a2[8];
    float b4t = __ldg(b4 + t);
#pragma unroll
    for (int rp = 0; rp < 8; rp++) r2a2[rp] = pack2(b4t, b4t);
    for (int c = 0; c < 4; c++) {
        for (int i = t; i < 256 * 64; i += 256) {
            int o = i >> 6, jj = i & 63;
            w4s[o * 65 + jj] = __ldg(w4 + o * 256 + c * 64 + jj);
        }
        __syncthreads();
#pragma unroll 4
        for (int jj = 0; jj < 64; jj++) {
            float w = w4s[t * 65 + jj];
            u64 w2p = pack2(w, w);
            const float2* rp1 = ((const float2*)r1f) + (c * 64 + jj) * 9;
#pragma unroll
            for (int rp = 0; rp < 8; rp++)
                r2a2[rp] = fma2(f2u(rp1[rp]), w2p, r2a2[rp]);
        }
        __syncthreads();
    }

    // stage C: reg = fc5 . relu(r2) + b5, reduce over 256 neurons
    float w5t = __ldg(w5 + t);
#pragma unroll
    for (int rp = 0; rp < 8; rp++) {
        float2 f = u2f(r2a2[rp]);
        float v0 = wsum(fmaxf(f.x, 0.f) * w5t);
        float v1 = wsum(fmaxf(f.y, 0.f) * w5t);
        if (lane == 0) {
            red[warp * 16 + 2 * rp] = v0;
            red[warp * 16 + 2 * rp + 1] = v1;
        }
    }
    __syncthreads();
    if (t < 16) {
        float s = __ldg(b5);
        for (int w = 0; w < 8; w++) s += red[w * 16 + t];
        int row = rbase + t;
        out[NROWS + row] = (g_sizef[row] != 0.f) ? s : 0.f;
    }
}

// ---------------- launcher ----------------
extern "C" void kernel_launch(void* const* d_in, const int* in_sizes, int n_in,
                              void* d_out, int out_size) {
    const float* x    = (const float*)d_in[0];
    const float* y    = (const float*)d_in[1];
    const float* wqkv = (const float*)d_in[2];
    const float* bqkv = (const float*)d_in[3];
    const float* wo   = (const float*)d_in[4];
    const float* bo   = (const float*)d_in[5];
    const float* ln1g = (const float*)d_in[6];
    const float* ln1b = (const float*)d_in[7];
    const float* ffw1 = (const float*)d_in[8];
    const float* ffb1 = (const float*)d_in[9];
    const float* ffw2 = (const float*)d_in[10];
    const float* ffb2 = (const float*)d_in[11];
    const float* ln2g = (const float*)d_in[12];
    const float* ln2b = (const float*)d_in[13];
    const float* fc1w = (const float*)d_in[14];
    const float* fc1b = (const float*)d_in[15];
    const float* fc2w = (const float*)d_in[16];
    const float* fc2b = (const float*)d_in[17];
    const float* fc3w = (const float*)d_in[18];
    const float* fc3b = (const float*)d_in[19];
    const float* fc4w = (const float*)d_in[20];
    const float* fc4b = (const float*)d_in[21];
    const float* fc5w = (const float*)d_in[22];
    const float* fc5b = (const float*)d_in[23];
    float* out = (float*)d_out;

    const int attn_smem = (4 * TILE_F2 * 2 + 512 + 196 + 16) * (int)sizeof(float);
    const int ffn_smem  = (2 * 7 * W1STRIDE + 28672 + 64 + 448 + 64 + 8) * (int)sizeof(float);
    const int h2_smem   = (13056 + 816 + 128 + 4608 + 16640) * (int)sizeof(float);
    cudaFuncSetAttribute(attn_kernel,  cudaFuncAttributeMaxDynamicSharedMemorySize, attn_smem);
    cudaFuncSetAttribute(ffn_kernel,   cudaFuncAttributeMaxDynamicSharedMemorySize, ffn_smem);
    cudaFuncSetAttribute(head2_kernel, cudaFuncAttributeMaxDynamicSharedMemorySize, h2_smem);

    for (int l = 0; l < 2; l++) {
        qkv_kernel<<<128, 256>>>(x, (l == 0) ? 1 : 0, wqkv + l * 588, bqkv + l * 42);
        prep_kernel<<<32, 256>>>();
        attn_kernel<<<128, 256, attn_smem>>>(x, (l == 0) ? 1 : 0,
                                             wo + l * 196, bo + l * 14,
                                             ln1g + l * 14, ln1b + l * 14);
        ffn_kernel<<<128, 256, ffn_smem>>>(ffw1 + l * 28672, ffb1 + l * 2048,
                                           ffw2 + l * 28672, ffb2 + l * 14,
                                           ln2g + l * 14, ln2b + l * 14);
    }
    head1_kernel<<<32, 256>>>(fc1w, fc1b, fc2w, fc2b, out);
    head2_kernel<<<512, 256, h2_smem>>>(x, y, fc3w, fc3b, fc4w, fc4b, fc5w, fc5b, out);
}

// round 3
// speedup vs baseline: 2.3981x; 1.1154x over previous
#include <cuda_runtime.h>
#include <stdint.h>

#define NROWS 8192
#define DM 14
#define MF 36
#define HH 256
#define FFD 2048
#define EPS 1e-5f
#define TK 512
#define KSTRIDE 514           // padded float2 stride per d2 row (conflict-free)
#define TILE_F2 (7 * KSTRIDE) // 3598 float2 per buffer

typedef unsigned long long u64;

// persistent scratch (device globals — no allocation allowed)
__device__ __align__(16) float g_h[NROWS * DM];
__device__ __align__(16) float g_q[NROWS * DM];   // pre-scaled by D^-0.5 * log2(e)
__device__ __align__(16) float g_k[NROWS * DM];
__device__ __align__(16) float g_v[NROWS * DM];
__device__ float g_sizef[NROWS];
__device__ float g_qn[NROWS];        // |q_scaled| per row
__device__ float g_kmaxpart[32];     // per-block max |k|^2

// ---------------- f32x2 helpers ----------------
__device__ __forceinline__ u64 f2u(float2 v) { union { float2 f; u64 u; } c; c.f = v; return c.u; }
__device__ __forceinline__ float2 u2f(u64 u) { union { float2 f; u64 u; } c; c.u = u; return c.f; }
__device__ __forceinline__ u64 pack2(float lo, float hi) { float2 v; v.x = lo; v.y = hi; return f2u(v); }
__device__ __forceinline__ u64 fma2(u64 a, u64 b, u64 c) {
    u64 d; asm("fma.rn.f32x2 %0,%1,%2,%3;" : "=l"(d) : "l"(a), "l"(b), "l"(c)); return d;
}
__device__ __forceinline__ u64 mul2(u64 a, u64 b) {
    u64 d; asm("mul.rn.f32x2 %0,%1,%2;" : "=l"(d) : "l"(a), "l"(b)); return d;
}
__device__ __forceinline__ u64 add2(u64 a, u64 b) {
    u64 d; asm("add.rn.f32x2 %0,%1,%2;" : "=l"(d) : "l"(a), "l"(b)); return d;
}
__device__ __forceinline__ float ex2f(float x) {
    float y; asm("ex2.approx.f32 %0,%1;" : "=f"(y) : "f"(x)); return y;
}
__device__ __forceinline__ void cp8(uint32_t dst, const void* src) {
    asm volatile("cp.async.ca.shared.global [%0], [%1], 8;" :: "r"(dst), "l"(src));
}
#define CP_COMMIT() asm volatile("cp.async.commit_group;")
#define CP_WAIT(N)  asm volatile("cp.async.wait_group %0;" :: "n"(N))

// ---------------- warp helpers ----------------
__device__ __forceinline__ float wsum(float v) {
#pragma unroll
    for (int o = 16; o; o >>= 1) v += __shfl_xor_sync(0xffffffffu, v, o);
    return v;
}
__device__ __forceinline__ float wmax(float v) {
#pragma unroll
    for (int o = 16; o; o >>= 1) v = fmaxf(v, __shfl_xor_sync(0xffffffffu, v, o));
    return v;
}

// ---------------- QKV projection ----------------
__global__ void __launch_bounds__(256, 1)
qkv_kernel(const float* __restrict__ x0, int use_x,
           const float* __restrict__ W, const float* __restrict__ b) {
    __shared__ float Ws[42 * 14];
    __shared__ float bs[42];
    __shared__ float hs[64 * 14];
    const float* hin = use_x ? x0 : g_h;
    const int t = threadIdx.x;
    const int rb = blockIdx.x * 64;
    for (int i = t; i < 588; i += 256) Ws[i] = W[i];
    if (t < 42) bs[t] = b[t];
    for (int i = t; i < 64 * 14; i += 256) hs[i] = hin[rb * DM + i];
    __syncthreads();
    const float scale = rsqrtf(14.0f) * 1.44269504f;   // fold log2(e) into q
    for (int idx = t; idx < 64 * 42; idx += 256) {
        int r = idx / 42, c = idx % 42;
        float s = bs[c];
#pragma unroll
        for (int d = 0; d < 14; d++) s = fmaf(hs[r * 14 + d], Ws[c * 14 + d], s);
        int row = rb + r;
        int dd = c % 14;
        if (c < 14)      g_q[row * DM + dd] = s * scale;
        else if (c < 28) g_k[row * DM + dd] = s;
        else             g_v[row * DM + dd] = s;
    }
}

// ---------------- prep: per-row |q|, global max |k|^2 (32 partials) ----------------
__global__ void __launch_bounds__(256, 1)
prep_kernel() {
    __shared__ float sp[8];
    const int t = threadIdx.x, lane = t & 31, warp = t >> 5;
    int r = blockIdx.x * 256 + t;
    float qn = 0.f, kn = 0.f;
#pragma unroll
    for (int d = 0; d < 14; d++) {
        float qf = g_q[r * DM + d]; qn = fmaf(qf, qf, qn);
        float kf = g_k[r * DM + d]; kn = fmaf(kf, kf, kn);
    }
    g_qn[r] = sqrtf(qn);
    kn = wmax(kn);
    if (lane == 0) sp[warp] = kn;
    __syncthreads();
    if (t == 0) {
        float m = sp[0];
#pragma unroll
        for (int w = 1; w < 8; w++) m = fmaxf(m, sp[w]);
        g_kmaxpart[blockIdx.x] = m;
    }
}

// ---------------- attention tile copy (cp.async, d-major float2, padded) ----------------
__device__ __forceinline__ void tile_cp(uint32_t ksb, uint32_t vsb, int buf, int cb, int t) {
    const float2* gk = ((const float2*)g_k) + cb * 7;
    const float2* gv = ((const float2*)g_v) + cb * 7;
    uint32_t kd = ksb + (uint32_t)buf * TILE_F2 * 8;
    uint32_t vd = vsb + (uint32_t)buf * TILE_F2 * 8;
#pragma unroll
    for (int s = 0; s < 14; s++) {
        int i = t + s * 256;                 // i < 3584
        int kk = i / 7;
        int d2 = i - kk * 7;
        uint32_t off = (uint32_t)(d2 * KSTRIDE + kk) * 8u;
        cp8(kd + off, gk + i);
        cp8(vd + off, gv + i);
    }
}

// ---------------- Flash attention (no-max softmax) + out-proj + residual + LN1 ----
// 128 persistent CTAs x 256 threads; 2 query-blocks of 32 per CTA; 4 queries/warp.
__global__ void __launch_bounds__(256, 1)
attn_kernel(const float* __restrict__ x0, int use_x,
            const float* __restrict__ Wo, const float* __restrict__ bo,
            const float* __restrict__ lng, const float* __restrict__ lnb) {
    extern __shared__ float sm[];
    float2* Ks2 = (float2*)sm;                 // 2 bufs x 3598 f2
    float2* Vs2 = (float2*)(sm + 2 * TILE_F2 * 2);
    float*  as_ = sm + 4 * TILE_F2 * 2;        // 32*16
    float*  wos = as_ + 512;                   // 196
    float*  bos = wos + 196;                   // 14

    const int t = threadIdx.x, lane = t & 31, warp = t >> 5;
    const uint32_t ksb = (uint32_t)__cvta_generic_to_shared(Ks2);
    const uint32_t vsb = (uint32_t)__cvta_generic_to_shared(Vs2);
    const float* hin = use_x ? x0 : g_h;

    if (t < 196) wos[t] = Wo[t];
    if (t < 14)  bos[t] = bo[t];

    // global max |k|
    float mk2 = 0.f;
#pragma unroll
    for (int i = 0; i < 32; i++) mk2 = fmaxf(mk2, __ldg(g_kmaxpart + i));
    const float maxk = sqrtf(mk2);

    for (int pass = 0; pass < 2; pass++) {
        const int qbase = (blockIdx.x + pass * 128) * 32;
        const int q0 = warp * 4;

        u64 q[4][7], o[4][7], init2[4];
        float l[4];
#pragma unroll
        for (int qi = 0; qi < 4; qi++) {
            int row = qbase + q0 + qi;
            const float2* qp = ((const float2*)g_q) + row * 7;
#pragma unroll
            for (int d2 = 0; d2 < 7; d2++) {
                q[qi][d2] = f2u(__ldg(qp + d2));
                o[qi][d2] = 0ull;
            }
            init2[qi] = pack2(-__ldg(g_qn + row) * maxk, 0.f);
            l[qi] = 0.f;
        }

        tile_cp(ksb, vsb, 0, 0, t);
        CP_COMMIT();

        for (int tile = 0; tile < 16; tile++) {
            if (tile < 15) {
                tile_cp(ksb, vsb, (tile + 1) & 1, (tile + 1) * TK, t);
                CP_COMMIT();
                CP_WAIT(1);
            } else {
                CP_WAIT(0);
            }
            __syncthreads();

            const float2* Kb = Ks2 + (tile & 1) * TILE_F2;
            const float2* Vb = Vs2 + (tile & 1) * TILE_F2;
#pragma unroll 2
            for (int kk = lane; kk < TK; kk += 32) {
                u64 k0 = f2u(Kb[0 * KSTRIDE + kk]);
                u64 k1 = f2u(Kb[1 * KSTRIDE + kk]);
                u64 k2 = f2u(Kb[2 * KSTRIDE + kk]);
                u64 k3 = f2u(Kb[3 * KSTRIDE + kk]);
                u64 k4 = f2u(Kb[4 * KSTRIDE + kk]);
                u64 k5 = f2u(Kb[5 * KSTRIDE + kk]);
                u64 k6 = f2u(Kb[6 * KSTRIDE + kk]);
                u64 v0 = f2u(Vb[0 * KSTRIDE + kk]);
                u64 v1 = f2u(Vb[1 * KSTRIDE + kk]);
                u64 v2 = f2u(Vb[2 * KSTRIDE + kk]);
                u64 v3 = f2u(Vb[3 * KSTRIDE + kk]);
                u64 v4 = f2u(Vb[4 * KSTRIDE + kk]);
                u64 v5 = f2u(Vb[5 * KSTRIDE + kk]);
                u64 v6 = f2u(Vb[6 * KSTRIDE + kk]);
#pragma unroll
                for (int qi = 0; qi < 4; qi++) {
                    u64 s2 = fma2(q[qi][0], k0, init2[qi]);
                    s2 = fma2(q[qi][1], k1, s2);
                    s2 = fma2(q[qi][2], k2, s2);
                    s2 = fma2(q[qi][3], k3, s2);
                    s2 = fma2(q[qi][4], k4, s2);
                    s2 = fma2(q[qi][5], k5, s2);
                    s2 = fma2(q[qi][6], k6, s2);
                    float2 sf = u2f(s2);
                    float p = ex2f(sf.x + sf.y);     // 2^(score*log2e - M) — bounded
                    l[qi] += p;
                    u64 p2 = pack2(p, p);
                    o[qi][0] = fma2(p2, v0, o[qi][0]);
                    o[qi][1] = fma2(p2, v1, o[qi][1]);
                    o[qi][2] = fma2(p2, v2, o[qi][2]);
                    o[qi][3] = fma2(p2, v3, o[qi][3]);
                    o[qi][4] = fma2(p2, v4, o[qi][4]);
                    o[qi][5] = fma2(p2, v5, o[qi][5]);
                    o[qi][6] = fma2(p2, v6, o[qi][6]);
                }
            }
            __syncthreads();
        }

        // cross-lane combine (shared M per query — simple sums)
#pragma unroll
        for (int qi = 0; qi < 4; qi++) {
            float ll = wsum(l[qi]);
            float av[14];
#pragma unroll
            for (int d2 = 0; d2 < 7; d2++) {
                float2 f = u2f(o[qi][d2]);
                av[2 * d2] = wsum(f.x);
                av[2 * d2 + 1] = wsum(f.y);
            }
            if (lane == 0) {
                float inv = 1.f / ll;
                float* ap = as_ + ((q0 + qi) << 4);
#pragma unroll
                for (int d = 0; d < 14; d++) ap[d] = av[d] * inv;
            }
        }
        __syncthreads();

        // out-projection + residual + LN1
        if (t < 32) {
            int row = qbase + t;
            float a[14];
#pragma unroll
            for (int d = 0; d < 14; d++) a[d] = as_[(t << 4) + d];
            float pre[14];
            float mu = 0.f;
#pragma unroll
            for (int d2 = 0; d2 < 14; d2++) {
                float ov = bos[d2];
#pragma unroll
                for (int d = 0; d < 14; d++) ov = fmaf(a[d], wos[d2 * 14 + d], ov);
                ov += hin[row * DM + d2];
                pre[d2] = ov;
                mu += ov;
            }
            mu *= (1.f / 14.f);
            float var = 0.f;
#pragma unroll
            for (int d = 0; d < 14; d++) { float z = pre[d] - mu; var = fmaf(z, z, var); }
            var *= (1.f / 14.f);
            float rs = rsqrtf(var + EPS);
#pragma unroll
            for (int d = 0; d < 14; d++)
                g_h[row * DM + d] = (pre[d] - mu) * rs * __ldg(lng + d) + __ldg(lnb + d);
        }
        __syncthreads();
    }
}

// ---------------- Fused FFN (14->2048->14) + residual + LN2 ----------------
// Warp-owned rows: each warp sweeps ALL 2048 hidden units for 4 rows.
// One reduction per sweep, no __syncthreads in the main loop.
__global__ void __launch_bounds__(256, 1)
ffn_kernel(const float* __restrict__ W1, const float* __restrict__ b1,
           const float* __restrict__ W2, const float* __restrict__ b2,
           const float* __restrict__ lng, const float* __restrict__ lnb) {
    extern __shared__ float sm[];
    float2* W1s = (float2*)sm;          // [j*7+dp] natural d-pairs, 14336 f2
    float2* W2p = W1s + 14336;          // [j*7+dp] = (W2[2dp][j], W2[2dp+1][j])

    const int t = threadIdx.x, lane = t & 31, warp = t >> 5;

    {
        const float2* W1g = (const float2*)W1;
        for (int i = t; i < 14336; i += 256) W1s[i] = W1g[i];
        for (int i = t; i < 14336; i += 256) {
            int dp = i / 2048, j = i - dp * 2048;
            float2 v;
            v.x = __ldg(W2 + (2 * dp) * 2048 + j);
            v.y = __ldg(W2 + (2 * dp + 1) * 2048 + j);
            W2p[j * 7 + dp] = v;
        }
    }
    __syncthreads();

    const int rbase = blockIdx.x * 64;
    for (int s = 0; s < 2; s++) {
        const int r0 = rbase + (s * 8 + warp) * 4;

        // broadcast-load 4 rows of h into registers (d-pair packed)
        u64 hB[4][7];
#pragma unroll
        for (int r = 0; r < 4; r++) {
            const float2* hp = ((const float2*)g_h) + (r0 + r) * 7;
#pragma unroll
            for (int dp = 0; dp < 7; dp++) hB[r][dp] = f2u(__ldg(hp + dp));
        }

        u64 acc[7][4];
#pragma unroll
        for (int dp = 0; dp < 7; dp++)
#pragma unroll
            for (int r = 0; r < 4; r++) acc[dp][r] = 0ull;

        for (int it = 0; it < 64; it++) {
            const int j = it * 32 + lane;
            const float b1j = __ldg(b1 + j);
            const float2* w1p = W1s + j * 7;
            u64 w1v[7];
#pragma unroll
            for (int dp = 0; dp < 7; dp++) w1v[dp] = f2u(w1p[dp]);
            float hj[4];
#pragma unroll
            for (int r = 0; r < 4; r++) {
                u64 s2 = mul2(hB[r][0], w1v[0]);
#pragma unroll
                for (int dp = 1; dp < 7; dp++) s2 = fma2(hB[r][dp], w1v[dp], s2);
                float2 sf = u2f(s2);
                hj[r] = fmaxf(sf.x + sf.y + b1j, 0.f);
            }
            const float2* w2pp = W2p + j * 7;
            u64 w2v[7];
#pragma unroll
            for (int dp = 0; dp < 7; dp++) w2v[dp] = f2u(w2pp[dp]);
#pragma unroll
            for (int r = 0; r < 4; r++) {
                u64 hd = pack2(hj[r], hj[r]);
#pragma unroll
                for (int dp = 0; dp < 7; dp++) acc[dp][r] = fma2(hd, w2v[dp], acc[dp][r]);
            }
        }

        // butterfly-reduce 28 u64 accumulators over 32 lanes (packed adds)
#pragma unroll
        for (int off = 16; off; off >>= 1) {
#pragma unroll
            for (int dp = 0; dp < 7; dp++)
#pragma unroll
                for (int r = 0; r < 4; r++) {
                    u64 other = __shfl_xor_sync(0xffffffffu, acc[dp][r], off);
                    acc[dp][r] = add2(acc[dp][r], other);
                }
        }

        // lanes 0-3 finalize one row each: bias + residual + LN2
#pragma unroll
        for (int r = 0; r < 4; r++) {
            if (lane == r) {
                float pre[14];
                float mu = 0.f;
#pragma unroll
                for (int dp = 0; dp < 7; dp++) {
                    float2 a = u2f(acc[dp][r]);
                    float2 h2 = u2f(hB[r][dp]);
                    float p0 = a.x + __ldg(b2 + 2 * dp) + h2.x;
                    float p1 = a.y + __ldg(b2 + 2 * dp + 1) + h2.y;
                    pre[2 * dp] = p0; pre[2 * dp + 1] = p1;
                    mu += p0 + p1;
                }
                mu *= (1.f / 14.f);
                float var = 0.f;
#pragma unroll
                for (int d = 0; d < 14; d++) { float z = pre[d] - mu; var = fmaf(z, z, var); }
                float rs = rsqrtf(var * (1.f / 14.f) + EPS);
                float* hw = g_h + (r0 + r) * DM;
#pragma unroll
                for (int d = 0; d < 14; d++)
                    hw[d] = (pre[d] - mu) * rs * __ldg(lng + d) + __ldg(lnb + d);
            }
        }
    }
}

// ---------------- head 1 ----------------
__global__ void __launch_bounds__(256, 1)
head1_kernel(const float* __restrict__ w1, const float* __restrict__ b1f,
             const float* __restrict__ w2, const float* __restrict__ b2f,
             float* __restrict__ out) {
    int n = blockIdx.x * 256 + threadIdx.x;
    float h[14];
#pragma unroll
    for (int d = 0; d < 14; d++) h[d] = g_h[n * DM + d];
    float size = __ldg(b2f);
#pragma unroll
    for (int d2 = 0; d2 < 14; d2++) {
        float s = __ldg(b1f + d2);
#pragma unroll
        for (int d = 0; d < 14; d++) s = fmaf(h[d], __ldg(w1 + d2 * 14 + d), s);
        size = fmaf(s, __ldg(w2 + d2), size);
    }
    out[n] = size;
    g_sizef[n] = (float)(int)size;
}

// ---------------- head 2: 51->256->256->1, w4 smem-staged, f32x2 ----------------
__global__ void __launch_bounds__(256, 1)
head2_kernel(const float* __restrict__ x, const float* __restrict__ y,
             const float* __restrict__ w3, const float* __restrict__ b3,
             const float* __restrict__ w4, const float* __restrict__ b4,
             const float* __restrict__ w5, const float* __restrict__ b5,
             float* __restrict__ out) {
    extern __shared__ float sm[];
    float* w3s   = sm;             // 13056 [t*51+i]
    float* ins   = w3s + 13056;    // 816
    float* red   = ins + 816;      // 128
    float* r1f   = red + 128;      // r1 pairs: 256 x 9 f2 = 4608 floats
    float* w4s   = r1f + 4608;     // 256 x 65 = 16640

    const int t = threadIdx.x, lane = t & 31, warp = t >> 5;
    const int rbase = blockIdx.x * 16;
    for (int i = t; i < 13056; i += 256) w3s[i] = w3[i];
    for (int i = t; i < 16 * 51; i += 256) {
        int r = i / 51, c = i % 51, row = rbase + r;
        float v;
        if (c == 0)      v = g_sizef[row];
        else if (c < 15) v = x[row * DM + c - 1];
        else             v = y[row * MF + c - 15];
        ins[i] = v;
    }
    __syncthreads();

    // stage A: r1[neuron t][16 rows]
    float r1a[16];
    float b3t = __ldg(b3 + t);
#pragma unroll
    for (int r = 0; r < 16; r++) r1a[r] = b3t;
    for (int i = 0; i < 51; i++) {
        float w = w3s[t * 51 + i];
#pragma unroll
        for (int r = 0; r < 16; r++) r1a[r] = fmaf(ins[r * 51 + i], w, r1a[r]);
    }
#pragma unroll
    for (int rp = 0; rp < 8; rp++) {
        float2 v;
        v.x = fmaxf(r1a[2 * rp], 0.f);
        v.y = fmaxf(r1a[2 * rp + 1], 0.f);
        ((float2*)r1f)[t * 9 + rp] = v;
    }
    __syncthreads();

    // stage B: r2[o=t][rows], w4 staged through smem chunks of 64
    u64 r2a2[8];
    float b4t = __ldg(b4 + t);
#pragma unroll
    for (int rp = 0; rp < 8; rp++) r2a2[rp] = pack2(b4t, b4t);
    for (int c = 0; c < 4; c++) {
        for (int i = t; i < 256 * 64; i += 256) {
            int o = i >> 6, jj = i & 63;
            w4s[o * 65 + jj] = __ldg(w4 + o * 256 + c * 64 + jj);
        }
        __syncthreads();
#pragma unroll 4
        for (int jj = 0; jj < 64; jj++) {
            float w = w4s[t * 65 + jj];
            u64 w2p = pack2(w, w);
            const float2* rp1 = ((const float2*)r1f) + (c * 64 + jj) * 9;
#pragma unroll
            for (int rp = 0; rp < 8; rp++)
                r2a2[rp] = fma2(f2u(rp1[rp]), w2p, r2a2[rp]);
        }
        __syncthreads();
    }

    // stage C: reg = fc5 . relu(r2) + b5, reduce over 256 neurons
    float w5t = __ldg(w5 + t);
#pragma unroll
    for (int rp = 0; rp < 8; rp++) {
        float2 f = u2f(r2a2[rp]);
        float v0 = wsum(fmaxf(f.x, 0.f) * w5t);
        float v1 = wsum(fmaxf(f.y, 0.f) * w5t);
        if (lane == 0) {
            red[warp * 16 + 2 * rp] = v0;
            red[warp * 16 + 2 * rp + 1] = v1;
        }
    }
    __syncthreads();
    if (t < 16) {
        float s = __ldg(b5);
        for (int w = 0; w < 8; w++) s += red[w * 16 + t];
        int row = rbase + t;
        out[NROWS + row] = (g_sizef[row] != 0.f) ? s : 0.f;
    }
}

// ---------------- launcher ----------------
extern "C" void kernel_launch(void* const* d_in, const int* in_sizes, int n_in,
                              void* d_out, int out_size) {
    const float* x    = (const float*)d_in[0];
    const float* y    = (const float*)d_in[1];
    const float* wqkv = (const float*)d_in[2];
    const float* bqkv = (const float*)d_in[3];
    const float* wo   = (const float*)d_in[4];
    const float* bo   = (const float*)d_in[5];
    const float* ln1g = (const float*)d_in[6];
    const float* ln1b = (const float*)d_in[7];
    const float* ffw1 = (const float*)d_in[8];
    const float* ffb1 = (const float*)d_in[9];
    const float* ffw2 = (const float*)d_in[10];
    const float* ffb2 = (const float*)d_in[11];
    const float* ln2g = (const float*)d_in[12];
    const float* ln2b = (const float*)d_in[13];
    const float* fc1w = (const float*)d_in[14];
    const float* fc1b = (const float*)d_in[15];
    const float* fc2w = (const float*)d_in[16];
    const float* fc2b = (const float*)d_in[17];
    const float* fc3w = (const float*)d_in[18];
    const float* fc3b = (const float*)d_in[19];
    const float* fc4w = (const float*)d_in[20];
    const float* fc4b = (const float*)d_in[21];
    const float* fc5w = (const float*)d_in[22];
    const float* fc5b = (const float*)d_in[23];
    float* out = (float*)d_out;

    const int attn_smem = (4 * TILE_F2 * 2 + 512 + 196 + 16) * (int)sizeof(float);
    const int ffn_smem  = (14336 * 2) * 2 * (int)sizeof(float);   // 229376 B
    const int h2_smem   = (13056 + 816 + 128 + 4608 + 16640) * (int)sizeof(float);
    cudaFuncSetAttribute(attn_kernel,  cudaFuncAttributeMaxDynamicSharedMemorySize, attn_smem);
    cudaFuncSetAttribute(ffn_kernel,   cudaFuncAttributeMaxDynamicSharedMemorySize, ffn_smem);
    cudaFuncSetAttribute(head2_kernel, cudaFuncAttributeMaxDynamicSharedMemorySize, h2_smem);

    for (int l = 0; l < 2; l++) {
        qkv_kernel<<<128, 256>>>(x, (l == 0) ? 1 : 0, wqkv + l * 588, bqkv + l * 42);
        prep_kernel<<<32, 256>>>();
        attn_kernel<<<128, 256, attn_smem>>>(x, (l == 0) ? 1 : 0,
                                             wo + l * 196, bo + l * 14,
                                             ln1g + l * 14, ln1b + l * 14);
        ffn_kernel<<<128, 256, ffn_smem>>>(ffw1 + l * 28672, ffb1 + l * 2048,
                                           ffw2 + l * 28672, ffb2 + l * 14,
                                           ln2g + l * 14, ln2b + l * 14);
    }
    head1_kernel<<<32, 256>>>(fc1w, fc1b, fc2w, fc2b, out);
    head2_kernel<<<512, 256, h2_smem>>>(x, y, fc3w, fc3b, fc4w, fc4b, fc5w, fc5b, out);
}